// round 8
// baseline (speedup 1.0000x reference)
#include <cuda_runtime.h>

#define B_   8
#define T_   512
#define K_   8
#define H_   128
#define DIN_ 100
#define DG_  50
#define NL_  20

// full state history per lane (device scratch; no allocation)
__device__ float d_hh[B_][T_][H_];
__device__ float d_ch[B_][T_][H_];

__device__ __forceinline__ float sigf(float x) { return 1.f / (1.f + expf(-x)); }

__global__ void __launch_bounds__(128, 1) lattice_kernel(
    const int* __restrict__ word,   const int* __restrict__ biword,
    const int* __restrict__ gids,   const int* __restrict__ gstarts,
    const int* __restrict__ gmask,  const int* __restrict__ mask,
    const float* __restrict__ wtab, const float* __restrict__ bwtab,
    const float* __restrict__ gtab,
    const float* __restrict__ W_ih, const float* __restrict__ W_hh,
    const float* __restrict__ b_lstm,
    const float* __restrict__ Wa_ih, const float* __restrict__ Wa_hh,
    const float* __restrict__ b_alpha,
    const float* __restrict__ Ww_ih, const float* __restrict__ Ww_hh,
    const float* __restrict__ b_word,
    const float* __restrict__ W_tag, const float* __restrict__ b_tag,
    float* __restrict__ out)
{
    __shared__ float sx[DIN_];
    __shared__ float si[H_], so[H_], sg[H_];
    __shared__ float hprev[H_], cprev[H_];
    __shared__ float cw[K_][H_];
    __shared__ float sl[NL_];
    __shared__ int sm[K_], ss[K_], sgi[K_], shw;

    int tid = threadIdx.x;
    int b   = blockIdx.x;

    hprev[tid] = 0.f;
    cprev[tid] = 0.f;
    __syncthreads();

    for (int j = 0; j < T_; j++) {
        // ---- load inputs for this step ----
        if (tid < DG_) {
            int w = word[b*T_ + j];
            w = max(0, min(w, 99999));
            sx[tid] = wtab[w*DG_ + tid];
        } else if (tid < DIN_) {
            int w = biword[b*T_ + j];
            w = max(0, min(w, 199999));
            sx[tid] = bwtab[w*DG_ + (tid - DG_)];
        }
        if (tid == 0) {
            int hw = 0;
            for (int k = 0; k < K_; k++) {
                int idx = (b*T_ + j)*K_ + k;
                int m = (gmask[idx] != 0);
                int s = gstarts[idx];  s = max(0, min(s, T_ - 1));
                int g = gids[idx];     g = max(0, min(g, 299999));
                sm[k] = m; ss[k] = s; sgi[k] = g;
                hw |= m;
            }
            shw = hw;
        }
        __syncthreads();

        // ---- char gates (i, o, g) and word memory cells ----
        {
            int h = tid;
            float ai = b_lstm[h], ao = b_lstm[H_ + h], ag = b_lstm[2*H_ + h];
            for (int d = 0; d < DIN_; d++) {
                float xv = sx[d];
                ai = fmaf(W_ih[h*DIN_ + d],         xv, ai);
                ao = fmaf(W_ih[(H_ + h)*DIN_ + d],  xv, ao);
                ag = fmaf(W_ih[(2*H_ + h)*DIN_ + d], xv, ag);
            }
            for (int d = 0; d < H_; d++) {
                float hv = hprev[d];
                ai = fmaf(W_hh[h*H_ + d],          hv, ai);
                ao = fmaf(W_hh[(H_ + h)*H_ + d],   hv, ao);
                ag = fmaf(W_hh[(2*H_ + h)*H_ + d], hv, ag);
            }
            si[h] = sigf(ai);
            so[h] = sigf(ao);
            sg[h] = tanhf(ag);

            for (int k = 0; k < K_; k++) {
                if (sm[k]) {
                    const float* hs = &d_hh[b][ss[k]][0];
                    const float* cs = &d_ch[b][ss[k]][0];
                    const float* ge = &gtab[sgi[k]*DG_];
                    float wi = b_word[h], wf = b_word[H_ + h], wg = b_word[2*H_ + h];
                    for (int d = 0; d < DG_; d++) {
                        float gv = ge[d];
                        wi = fmaf(Ww_ih[h*DG_ + d],          gv, wi);
                        wf = fmaf(Ww_ih[(H_ + h)*DG_ + d],   gv, wf);
                        wg = fmaf(Ww_ih[(2*H_ + h)*DG_ + d], gv, wg);
                    }
                    for (int d = 0; d < H_; d++) {
                        float hv = hs[d];
                        wi = fmaf(Ww_hh[h*H_ + d],          hv, wi);
                        wf = fmaf(Ww_hh[(H_ + h)*H_ + d],   hv, wf);
                        wg = fmaf(Ww_hh[(2*H_ + h)*H_ + d], hv, wg);
                    }
                    cw[k][h] = fmaf(sigf(wf), cs[h], sigf(wi) * tanhf(wg));
                }
            }
        }
        __syncthreads();

        // ---- gated aggregation + state update ----
        {
            int h = tid;
            float num = 0.f, den = 0.f;
            if (shw) {
                float xa = b_alpha[h];
                for (int d = 0; d < DIN_; d++)
                    xa = fmaf(Wa_ih[h*DIN_ + d], sx[d], xa);
                for (int k = 0; k < K_; k++) {
                    if (sm[k]) {
                        float dot = xa;
                        for (int d = 0; d < H_; d++)
                            dot = fmaf(Wa_hh[h*H_ + d], cw[k][d], dot);
                        float e = expf(sigf(dot));
                        num = fmaf(e, cw[k][h], num);
                        den += e;
                    }
                }
            }
            float ii = si[h], gg = sg[h], cp = cprev[h];
            float cn;
            if (shw) { float wc = expf(ii); cn = (wc*gg + num) / (wc + den); }
            else     cn = fmaf(ii, gg, (1.f - ii)*cp);
            float hn = so[h] * tanhf(cn);
            hprev[h] = hn;
            cprev[h] = cn;
            d_hh[b][j][h] = hn;
            d_ch[b][j][h] = cn;
        }
        __syncthreads();

        // ---- logits: concat(fwd,fwd) @ W_tag.T + b_tag, inline argmax ----
        if (tid < NL_) {
            float a = b_tag[tid];
            for (int q = 0; q < H_; q++)
                a = fmaf(W_tag[tid*256 + q] + W_tag[tid*256 + 128 + q], hprev[q], a);
            sl[tid] = a;
        }
        __syncthreads();
        if (tid == 0) {
            float best = sl[0]; int bi = 0;
            for (int l = 1; l < NL_; l++)
                if (sl[l] > best) { best = sl[l]; bi = l; }
            out[b*T_ + j] = (float)(mask[b*T_ + j] * bi);   // OUTPUT AS FLOAT32
        }
        __syncthreads();
    }
}

extern "C" void kernel_launch(void* const* d_in, const int* in_sizes, int n_in,
                              void* d_out, int out_size) {
    // positional order exactly as the reference setup_inputs() dict
    const int*   word       = (const int*)d_in[0];
    const int*   biword     = (const int*)d_in[1];
    const int*   gaz_ids    = (const int*)d_in[2];
    const int*   gaz_starts = (const int*)d_in[3];
    const int*   gaz_mask   = (const int*)d_in[4];
    const int*   mask       = (const int*)d_in[5];
    const float* wtab       = (const float*)d_in[6];
    const float* bwtab      = (const float*)d_in[7];
    const float* gtab       = (const float*)d_in[8];
    const float* W_ih       = (const float*)d_in[9];
    const float* W_hh       = (const float*)d_in[10];
    const float* b_lstm     = (const float*)d_in[11];
    const float* Wa_ih      = (const float*)d_in[12];
    const float* Wa_hh      = (const float*)d_in[13];
    const float* b_alpha    = (const float*)d_in[14];
    const float* Ww_ih      = (const float*)d_in[15];
    const float* Ww_hh      = (const float*)d_in[16];
    const float* b_word     = (const float*)d_in[17];
    const float* W_tag      = (const float*)d_in[18];
    const float* b_tag      = (const float*)d_in[19];

    lattice_kernel<<<B_, 128>>>(word, biword, gaz_ids, gaz_starts, gaz_mask, mask,
                                wtab, bwtab, gtab,
                                W_ih, W_hh, b_lstm,
                                Wa_ih, Wa_hh, b_alpha,
                                Ww_ih, Ww_hh, b_word,
                                W_tag, b_tag, (float*)d_out);
}

// round 9
// speedup vs baseline: 26.0442x; 26.0442x over previous
#include <cuda_runtime.h>
#include <cstddef>

#define B_   8
#define T_   512
#define K_   8
#define H_   128
#define G3_  384
#define DIN_ 100
#define DG_  50
#define NL_  20

// device scratch (no allocation allowed)
__device__ __align__(16) float g_xW  [B_*T_*G3_];
__device__ __align__(16) float g_xWa [B_*T_*H_];
__device__ __align__(16) float g_gW  [B_*T_*K_*G3_];
__device__ __align__(16) float g_WwP [32*G3_*4];   // Ww_hh packed [d/4][g][4]
__device__ __align__(16) float g_WaP [32*H_*4];    // Wa_hh packed [d/4][h][4]
__device__ __align__(16) float g_Wt2 [NL_*H_];     // W_tag[:, :128] + W_tag[:, 128:]
__device__ __align__(16) float g_WihT [DIN_*G3_];
__device__ __align__(16) float g_WaihT[DIN_*H_];
__device__ __align__(16) float g_WwihT[DG_*G3_];

extern __shared__ float smem_dyn[];

__global__ void pack_kernel(const float* __restrict__ Ww_hh, const float* __restrict__ Wa_hh,
                            const float* __restrict__ W_tag, const float* __restrict__ W_ih,
                            const float* __restrict__ Wa_ih, const float* __restrict__ Ww_ih) {
    int stride = gridDim.x * blockDim.x;
    int t0 = blockIdx.x * blockDim.x + threadIdx.x;
    for (int i = t0; i < G3_*H_; i += stride) {
        int g = i >> 7, d = i & 127;
        g_WwP[(d >> 2)*(G3_*4) + (g << 2) + (d & 3)] = Ww_hh[i];
    }
    for (int i = t0; i < H_*H_; i += stride) {
        int h = i >> 7, d = i & 127;
        g_WaP[(d >> 2)*(H_*4) + (h << 2) + (d & 3)] = Wa_hh[i];
    }
    for (int i = t0; i < NL_*H_; i += stride) {
        int l = i >> 7, h = i & 127;
        g_Wt2[i] = W_tag[l*256 + h] + W_tag[l*256 + 128 + h];
    }
    for (int i = t0; i < DIN_*G3_; i += stride) {
        int g = i / DIN_, d = i - g*DIN_;
        g_WihT[d*G3_ + g] = W_ih[i];
    }
    for (int i = t0; i < DIN_*H_; i += stride) {
        int h = i / DIN_, d = i - h*DIN_;
        g_WaihT[d*H_ + h] = Wa_ih[i];
    }
    for (int i = t0; i < DG_*G3_; i += stride) {
        int g = i / DG_, d = i - g*DG_;
        g_WwihT[d*G3_ + g] = Ww_ih[i];
    }
}

__global__ void __launch_bounds__(384, 1) xw_kernel(
    const int* __restrict__ word, const int* __restrict__ biword,
    const float* __restrict__ wtab, const float* __restrict__ bwtab,
    const float* __restrict__ b_lstm, const float* __restrict__ b_alpha)
{
    __shared__ float sx[16][DIN_];
    int tid = threadIdx.x;
    for (int base = blockIdx.x*16; base < B_*T_; base += gridDim.x*16) {
        for (int t = tid; t < 16*DIN_; t += 384) {
            int it = t / DIN_, d = t - it*DIN_;
            int item = base + it;
            sx[it][d] = (d < DG_) ? wtab[(size_t)word[item]*DG_ + d]
                                  : bwtab[(size_t)biword[item]*DG_ + (d - DG_)];
        }
        __syncthreads();
        int g = tid;
        float acc[16], acca[16];
        #pragma unroll
        for (int it = 0; it < 16; it++) { acc[it] = 0.f; acca[it] = 0.f; }
        for (int d = 0; d < DIN_; d++) {
            float w  = g_WihT[d*G3_ + g];
            float wa = (g < H_) ? g_WaihT[d*H_ + g] : 0.f;
            #pragma unroll
            for (int it = 0; it < 16; it++) {
                float xv = sx[it][d];
                acc[it]  = fmaf(w,  xv, acc[it]);
                acca[it] = fmaf(wa, xv, acca[it]);
            }
        }
        float bl = b_lstm[g];
        for (int it = 0; it < 16; it++) g_xW[(base + it)*G3_ + g] = acc[it] + bl;
        if (g < H_) {
            float ba = b_alpha[g];
            for (int it = 0; it < 16; it++) g_xWa[(base + it)*H_ + g] = acca[it] + ba;
        }
        __syncthreads();
    }
}

__global__ void __launch_bounds__(384, 1) gw_kernel(
    const int* __restrict__ gaz_ids, const int* __restrict__ gaz_mask,
    const float* __restrict__ gtab, const float* __restrict__ b_word)
{
    __shared__ float sg[16][DG_];
    __shared__ int smsk[16];
    int tid = threadIdx.x;
    for (int base = blockIdx.x*16; base < B_*T_*K_; base += gridDim.x*16) {
        if (tid < 16) smsk[tid] = (gaz_mask[base + tid] != 0);
        __syncthreads();
        for (int t = tid; t < 16*DG_; t += 384) {
            int it = t / DG_, d = t - it*DG_;
            sg[it][d] = smsk[it] ? gtab[(size_t)gaz_ids[base + it]*DG_ + d] : 0.f;
        }
        __syncthreads();
        int g = tid;
        float acc[16];
        #pragma unroll
        for (int it = 0; it < 16; it++) acc[it] = 0.f;
        for (int d = 0; d < DG_; d++) {
            float w = g_WwihT[d*G3_ + g];
            #pragma unroll
            for (int it = 0; it < 16; it++) acc[it] = fmaf(w, sg[it][d], acc[it]);
        }
        float bw = b_word[g];
        for (int it = 0; it < 16; it++)
            if (smsk[it]) g_gW[(size_t)(base + it)*G3_ + g] = acc[it] + bw;
        __syncthreads();
    }
}

__global__ void __launch_bounds__(384, 1) rec_kernel(
    const float* __restrict__ W_hh,
    const int* __restrict__ gmask, const int* __restrict__ gstart,
    const float* __restrict__ b_tag, const int* __restrict__ mask,
    float* __restrict__ out)
{
    float* sW     = smem_dyn;            // 49152 floats: W_hh packed [d/4][g][4]
    float* vhring = sW + 49152;          // 8 x 384
    float* hring  = vhring + 3072;       // 8 x 128
    float* cring  = hring + 1024;        // 8 x 128
    float* i_s    = cring + 1024;        // 128
    float* o_s    = i_s + 128;
    float* gt_s   = o_s + 128;
    float* cw     = gt_s + 128;          // 8 x 128
    float* part   = cw + 1024;           // 8 x 128 (alpha partials / logit partials)
    int*   si     = (int*)(part + 1024);
    int* act_k  = si;
    int* act_s  = si + 8;
    int* p_nact = si + 16;
    int* p_hw   = si + 17;

    int tid = threadIdx.x;
    int b   = blockIdx.x;

    for (int i = tid; i < G3_*H_; i += 384) {
        int g = i >> 7, d = i & 127;
        sW[(d >> 2)*(G3_*4) + (g << 2) + (d & 3)] = __ldg(&W_hh[i]);
    }
    for (int i = tid; i < 3072 + 1024 + 1024; i += 384) vhring[i] = 0.f;
    __syncthreads();

    const float4* WwP = (const float4*)g_WwP;
    const float4* WaP = (const float4*)g_WaP;
    const float4* sW4 = (const float4*)sW;
    const float4* cw4 = (const float4*)cw;

    float acc[8];
    int h = tid & 127;
    int p = tid >> 7;

    for (int j = 0; j < T_; j++) {
        int pslot = (j + 7) & 7;

        // Stage A: g3 = xW + W_hh@h_prev ; vh_{j-1} = Ww_hh@h_prev ; edge compaction
        {
            int g = tid;
            const float4* hp4 = (const float4*)(hring + pslot*H_);
            float a1 = 0.f, a2 = 0.f;
            #pragma unroll
            for (int c = 0; c < 32; c++) {
                float4 w1 = sW4[c*G3_ + g];
                float4 w2 = WwP[c*G3_ + g];
                float4 hh = hp4[c];
                a1 = fmaf(w1.x, hh.x, fmaf(w1.y, hh.y, fmaf(w1.z, hh.z, fmaf(w1.w, hh.w, a1))));
                a2 = fmaf(w2.x, hh.x, fmaf(w2.y, hh.y, fmaf(w2.z, hh.z, fmaf(w2.w, hh.w, a2))));
            }
            float gv = g_xW[(b*T_ + j)*G3_ + g] + a1;
            if (g < 128)      i_s[g]        = 1.f / (1.f + expf(-gv));
            else if (g < 256) o_s[g - 128]  = 1.f / (1.f + expf(-gv));
            else              gt_s[g - 256] = tanhf(gv);
            vhring[pslot*G3_ + g] = a2;

            if (tid >= 352) {
                int lane = tid - 352;
                int m = 0, s = 0;
                if (lane < 8) {
                    int idx = (b*T_ + j)*K_ + lane;
                    m = (gmask[idx] != 0);
                    s = gstart[idx];
                }
                unsigned bal = __ballot_sync(0xffffffffu, m != 0);
                if (lane < 8 && m) {
                    int pos = __popc(bal & ((1u << lane) - 1u));
                    act_k[pos] = lane;
                    act_s[pos] = s;
                }
                if (lane == 0) { *p_nact = __popc(bal); *p_hw = bal ? 1 : 0; }
            }
        }
        __syncthreads();
        int nact = *p_nact;
        int nr = (nact + 3) & ~3;

        // Stage B: word cells (3 edges per pass across p-groups) + zero-pad
        for (int base = 0; base < nact; base += 3) {
            int kk = base + p;
            if (kk < nact) {
                int k = act_k[kk], s = act_s[kk], slot = s & 7;
                const float* gw = g_gW + (size_t)((b*T_ + j)*K_ + k)*G3_;
                float iw = gw[h]       + vhring[slot*G3_ + h];
                float fw = gw[128 + h] + vhring[slot*G3_ + 128 + h];
                float gg = gw[256 + h] + vhring[slot*G3_ + 256 + h];
                float cs = cring[slot*H_ + h];
                float sf  = 1.f / (1.f + expf(-fw));
                float siw = 1.f / (1.f + expf(-iw));
                cw[kk*H_ + h] = fmaf(sf, cs, siw * tanhf(gg));
            }
        }
        { int kkz = nact + p; if (kkz < nr) cw[kkz*H_ + h] = 0.f; }
        __syncthreads();

        // Stage C phase 1: Wa_hh@c_w, d-range split over p in {0,1}
        if (nact > 0 && p < 2) {
            #pragma unroll
            for (int r = 0; r < 8; r++) acc[r] = 0.f;
            #pragma unroll 4
            for (int cc = 0; cc < 16; cc++) {
                int c = (p << 4) + cc;
                float4 w = WaP[c*H_ + h];
                #pragma unroll
                for (int r = 0; r < 8; r++) {
                    if (r < nr) {
                        float4 cv = cw4[r*32 + c];
                        acc[r] = fmaf(w.x, cv.x, fmaf(w.y, cv.y,
                                 fmaf(w.z, cv.z, fmaf(w.w, cv.w, acc[r]))));
                    }
                }
            }
            if (p == 1) {
                #pragma unroll
                for (int r = 0; r < 8; r++)
                    if (r < nact) part[r*H_ + h] = acc[r];
            }
        }
        __syncthreads();

        // Stage C phase 2 + Stage D: alpha aggregate, state update
        if (tid < 128) {
            float num = 0.f, den = 0.f;
            if (nact > 0) {
                float xwa = g_xWa[(b*T_ + j)*H_ + h];
                #pragma unroll
                for (int r = 0; r < 8; r++) {
                    if (r < nact) {
                        float dotv = acc[r] + part[r*H_ + h];
                        float al = 1.f / (1.f + expf(-(xwa + dotv)));
                        float e = expf(al);
                        num = fmaf(e, cw[r*H_ + h], num);
                        den += e;
                    }
                }
            }
            float ii = i_s[h], oo = o_s[h], gg = gt_s[h];
            float cprev = cring[pslot*H_ + h];
            float cnew;
            if (*p_hw) { float wc = expf(ii); cnew = (wc*gg + num) / (wc + den); }
            else       cnew = fmaf(ii, gg, (1.f - ii)*cprev);
            float hnew = oo * tanhf(cnew);
            hring[(j & 7)*H_ + h] = hnew;
            cring[(j & 7)*H_ + h] = cnew;
        }
        __syncthreads();

        // Stage E: logits + argmax (FLOAT output)
        if (tid < NL_*8) {
            int l = tid >> 3, seg = tid & 7;
            const float* w  = g_Wt2 + l*H_ + seg*16;
            const float* hv = hring + (j & 7)*H_ + seg*16;
            float a = 0.f;
            #pragma unroll
            for (int q = 0; q < 16; q++) a = fmaf(w[q], hv[q], a);
            part[tid] = a;
        }
        __syncthreads();
        if (tid < 32) {
            float v = -3.4e38f;
            if (tid < NL_) {
                float s = __ldg(&b_tag[tid]);
                #pragma unroll
                for (int q = 0; q < 8; q++) s += part[tid*8 + q];
                v = s;
            }
            int bi = tid;
            #pragma unroll
            for (int off = 16; off; off >>= 1) {
                float ov = __shfl_xor_sync(0xffffffffu, v, off);
                int   oi = __shfl_xor_sync(0xffffffffu, bi, off);
                if (ov > v || (ov == v && oi < bi)) { v = ov; bi = oi; }
            }
            if (tid == 0) out[b*T_ + j] = (float)(mask[b*T_ + j] * bi);
        }
        // safe: next write to 'part' (stage C of iter j+1) is 2 barriers after this read
    }
}

#define REC_SMEM ((49152 + 3072 + 1024 + 1024 + 384 + 1024 + 1024 + 32) * 4)

extern "C" void kernel_launch(void* const* d_in, const int* in_sizes, int n_in,
                              void* d_out, int out_size) {
    const int*   word       = (const int*)d_in[0];
    const int*   biword     = (const int*)d_in[1];
    const int*   gaz_ids    = (const int*)d_in[2];
    const int*   gaz_starts = (const int*)d_in[3];
    const int*   gaz_mask   = (const int*)d_in[4];
    const int*   mask       = (const int*)d_in[5];
    const float* wtab       = (const float*)d_in[6];
    const float* bwtab      = (const float*)d_in[7];
    const float* gtab       = (const float*)d_in[8];
    const float* W_ih       = (const float*)d_in[9];
    const float* W_hh       = (const float*)d_in[10];
    const float* b_lstm     = (const float*)d_in[11];
    const float* Wa_ih      = (const float*)d_in[12];
    const float* Wa_hh      = (const float*)d_in[13];
    const float* b_alpha    = (const float*)d_in[14];
    const float* Ww_ih      = (const float*)d_in[15];
    const float* Ww_hh      = (const float*)d_in[16];
    const float* b_word     = (const float*)d_in[17];
    const float* W_tag      = (const float*)d_in[18];
    const float* b_tag      = (const float*)d_in[19];

    cudaFuncSetAttribute(rec_kernel, cudaFuncAttributeMaxDynamicSharedMemorySize, REC_SMEM);

    pack_kernel<<<64, 256>>>(Ww_hh, Wa_hh, W_tag, W_ih, Wa_ih, Ww_ih);
    xw_kernel<<<256, 384>>>(word, biword, wtab, bwtab, b_lstm, b_alpha);
    gw_kernel<<<256, 384>>>(gaz_ids, gaz_mask, gtab, b_word);
    rec_kernel<<<8, 384, REC_SMEM>>>(W_hh, gaz_mask, gaz_starts, b_tag, mask, (float*)d_out);
}